// round 13
// baseline (speedup 1.0000x reference)
#include <cuda_runtime.h>
#include <cuda_bf16.h>
#include <cuda_fp16.h>
#include <math.h>
#include <stdint.h>

#define N_NODES 100000
#define N_EDGES 800000
#define D_DATA  100
#define H_DIM   256
#define N_CLS   47
#define K_STEPS 10
#define D_VEC   25          // D_DATA / 4 float4s per row
#define ROW_BYTES 400

// ---------------- static device scratch ----------------
__device__ float  g_buf0[(size_t)N_NODES * D_DATA];   // 40 MB (init = xn)
__device__ float  g_buf1[(size_t)N_NODES * D_DATA];   // 40 MB
__device__ __half g_xnh[(size_t)N_NODES * D_DATA];    // 20 MB (fp16 teleport term)
__device__ int    d_cnt[N_NODES];
__device__ int2   d_ptr2[N_NODES];                    // (begin, end)
__device__ int    d_cursor[N_NODES];
__device__ float  d_norm[N_NODES];
__device__ float  d_n2[N_NODES];
__device__ int    d_csr[N_EDGES];                     // BYTE offsets: src*400

// ---------------- CSR build ----------------
// d_cnt is zero at entry of every call (zero-init at load; fill_kernel re-zeros).
__global__ void count_kernel(const int* __restrict__ dst) {
    int e = blockIdx.x * blockDim.x + threadIdx.x;
    if (e < N_EDGES) atomicAdd(&d_cnt[dst[e]], 1);
}

#define SCAN_T 1024
#define SCAN_CH 98
__global__ void scan_kernel() {
    __shared__ int part[SCAN_T];
    int t = threadIdx.x;
    int beg = t * SCAN_CH;
    int end = beg + SCAN_CH; if (end > N_NODES) end = N_NODES;
    if (beg > N_NODES) beg = N_NODES;
    int s = 0;
    for (int i = beg; i < end; i++) s += d_cnt[i];
    part[t] = s;
    __syncthreads();
    for (int off = 1; off < SCAN_T; off <<= 1) {
        int v = (t >= off) ? part[t - off] : 0;
        __syncthreads();
        part[t] += v;
        __syncthreads();
    }
    int run = part[t] - s;
    for (int i = beg; i < end; i++) {
        int c = d_cnt[i];
        d_ptr2[i] = make_int2(run, run + c);
        d_cursor[i] = run;
        run += c;
        float nm = rsqrtf(fmaxf((float)c, 1.0f));
        d_norm[i] = nm;
        d_n2[i] = nm * nm;
    }
}

// scatter BYTE offsets into CSR; zero d_cnt; init buf0 = xn (fp32), xnh = xn (fp16)
#define FILL_THREADS_TOTAL (3125 * 256)   // == N_EDGES
__global__ void fill_kernel(const int* __restrict__ src, const int* __restrict__ dst,
                            const float4* __restrict__ x) {
    int e = blockIdx.x * blockDim.x + threadIdx.x;
    if (e < N_EDGES) {
        int d = dst[e];
        int p = atomicAdd(&d_cursor[d], 1);
        d_csr[p] = src[e] * ROW_BYTES;
    }
    if (e < N_NODES) d_cnt[e] = 0;
    for (int i = e; i < N_NODES * D_VEC; i += FILL_THREADS_TOTAL) {
        int node = i / D_VEC;
        float nm = d_norm[node];
        float4 v = __ldcs(&x[i]);
        v.x *= nm; v.y *= nm; v.z *= nm; v.w *= nm;
        ((float4*)g_buf0)[i] = v;
        __half2 h0 = __floats2half2_rn(v.x, v.y);
        __half2 h1 = __floats2half2_rn(v.z, v.w);
        uint2 pk;
        pk.x = *(unsigned int*)&h0;
        pk.y = *(unsigned int*)&h1;
        ((uint2*)g_xnh)[i] = pk;
    }
}

// ---------------- propagation ----------------
// Uniform step: gout = s1 * sum_e gin[src] + 0.1 * term
//   t < K-1: s1 = 0.9*n2[i], term = xnh (fp16)   (g-space)
//   t = K-1: s1 = 0.9*norm[i], term = x (fp32)   (h output)
__global__ void prop_kernel(const char* __restrict__ gin_bytes,
                            float4* __restrict__ gout,
                            const uint2* __restrict__ term_h,
                            const float4* __restrict__ term_f,
                            int last) {
    int warp = (blockIdx.x * blockDim.x + threadIdx.x) >> 5;
    int lane = threadIdx.x & 31;
    if (warp >= N_NODES) return;
    int2 pe = __ldg(&d_ptr2[warp]);
    int beg = pe.x, end = pe.y;

    const char* gbl = gin_bytes + lane * 16;   // per-lane base
    float a0 = 0.f, a1 = 0.f, a2 = 0.f, a3 = 0.f;
    bool act = lane < D_VEC;

    for (int base = beg; base < end; base += 32) {
        int n = end - base; if (n > 32) n = 32;
        int off = (lane < n) ? __ldg(&d_csr[base + lane]) : 0;   // byte offset
        #pragma unroll 4
        for (int e = 0; e < n; e++) {
            int o = __shfl_sync(0xffffffffu, off, e);
            if (act) {
                float4 v = *(const float4*)(gbl + o);
                a0 += v.x; a1 += v.y; a2 += v.z; a3 += v.w;
            }
        }
    }

    float s1 = 0.9f * (last ? d_norm[warp] : d_n2[warp]);

    if (act) {
        float4 tv;
        if (last) {
            tv = __ldcs(&term_f[warp * D_VEC + lane]);
        } else {
            uint2 r = __ldcs(&term_h[warp * D_VEC + lane]);
            float2 f0 = __half22float2(*(__half2*)&r.x);
            float2 f1 = __half22float2(*(__half2*)&r.y);
            tv = make_float4(f0.x, f0.y, f1.x, f1.y);
        }
        float4 o;
        o.x = s1 * a0 + 0.1f * tv.x;
        o.y = s1 * a1 + 0.1f * tv.y;
        o.z = s1 * a2 + 0.1f * tv.z;
        o.w = s1 * a3 + 0.1f * tv.w;
        if (last) __stcs(&gout[warp * D_VEC + lane], o);
        else      gout[warp * D_VEC + lane] = o;
    }
}

// ---------------- MLP via warp-level mma.sync (fp16 in, fp32 accum) ----------
// (unchanged, best-measured R10 version)
#define TILE_M 128
#define MLP_THREADS 512
#define HS_W   60
#define W1T_W  60
#define ZS_W   132
#define W2T_W  132

#define OFF_HS   0
#define OFF_W1T  30720
#define OFF_ZS   92160
#define OFF_W2T  159744
#define OFF_B1   185088
#define OFF_B2   186112
#define MLP_SMEM_BYTES 186304

__device__ __forceinline__ void mma16816(float& c0, float& c1, float& c2, float& c3,
                                         uint32_t a0, uint32_t a1, uint32_t a2, uint32_t a3,
                                         uint32_t b0, uint32_t b1) {
    asm volatile(
        "mma.sync.aligned.m16n8k16.row.col.f32.f16.f16.f32 "
        "{%0,%1,%2,%3}, {%4,%5,%6,%7}, {%8,%9}, {%0,%1,%2,%3};"
        : "+f"(c0), "+f"(c1), "+f"(c2), "+f"(c3)
        : "r"(a0), "r"(a1), "r"(a2), "r"(a3), "r"(b0), "r"(b1));
}

__device__ __forceinline__ uint32_t pack_h2(float lo, float hi) {
    __half2 h = __floats2half2_rn(lo, hi);
    return *(uint32_t*)&h;
}

__global__ void __launch_bounds__(MLP_THREADS, 1)
mlp_mma_kernel(const float* __restrict__ h,
               const float* __restrict__ W1, const float* __restrict__ b1,
               const float* __restrict__ W2, const float* __restrict__ b2,
               float* __restrict__ out) {
    extern __shared__ char smc[];
    uint32_t* hsW  = (uint32_t*)(smc + OFF_HS);
    uint32_t* w1W  = (uint32_t*)(smc + OFF_W1T);
    uint32_t* zsW  = (uint32_t*)(smc + OFF_ZS);
    uint32_t* w2W  = (uint32_t*)(smc + OFF_W2T);
    float*    b1s  = (float*)(smc + OFF_B1);
    float*    b2s  = (float*)(smc + OFF_B2);

    int tid = threadIdx.x;
    int wid = tid >> 5, lane = tid & 31;
    int gr = lane >> 2, tc = lane & 3;
    int wp = wid >> 1, half = wid & 1;
    int m0 = wp * 16;

    for (int i = tid; i < 256 * W1T_W; i += MLP_THREADS) {
        int j = i / W1T_W, kw = i % W1T_W;
        int k = kw * 2;
        float lo = (k     < D_DATA) ? W1[k * H_DIM + j]       : 0.f;
        float hi = (k + 1 < D_DATA) ? W1[(k + 1) * H_DIM + j] : 0.f;
        w1W[i] = pack_h2(lo, hi);
    }
    for (int i = tid; i < 48 * W2T_W; i += MLP_THREADS) {
        int c = i / W2T_W, jw = i % W2T_W;
        int j = jw * 2;
        float lo = (c < N_CLS && j     < H_DIM) ? W2[j * N_CLS + c]       : 0.f;
        float hi = (c < N_CLS && j + 1 < H_DIM) ? W2[(j + 1) * N_CLS + c] : 0.f;
        w2W[i] = pack_h2(lo, hi);
    }
    for (int i = tid; i < H_DIM; i += MLP_THREADS) b1s[i] = b1[i];
    if (tid < 48) b2s[tid] = (tid < N_CLS) ? b2[tid] : 0.f;
    __syncthreads();

    int n_tiles = (N_NODES + TILE_M - 1) / TILE_M;   // 782
    for (int tile = blockIdx.x; tile < n_tiles; tile += gridDim.x) {
        int node0 = tile * TILE_M;

        for (int i = tid; i < TILE_M * HS_W; i += MLP_THREADS) {
            int m = i / HS_W, kw = i % HS_W;
            int k = kw * 2;
            int node = node0 + m;
            uint32_t v = 0;
            if (node < N_NODES && k < D_DATA) {
                float2 f = *(const float2*)(h + (size_t)node * D_DATA + k);
                v = pack_h2(f.x, f.y);
            }
            hsW[i] = v;
        }
        __syncthreads();

        #pragma unroll 1
        for (int chh = 0; chh < 2; chh++) {
            int n0 = (half * 2 + chh) * 64;
            float acc[8][4];
            #pragma unroll
            for (int nb = 0; nb < 8; nb++)
                #pragma unroll
                for (int q = 0; q < 4; q++) acc[nb][q] = 0.f;

            #pragma unroll
            for (int kb = 0; kb < 7; kb++) {
                int kwb = kb * 8 + tc;
                uint32_t a0 = hsW[(m0 + gr) * HS_W + kwb];
                uint32_t a1 = hsW[(m0 + gr + 8) * HS_W + kwb];
                uint32_t a2 = hsW[(m0 + gr) * HS_W + kwb + 4];
                uint32_t a3 = hsW[(m0 + gr + 8) * HS_W + kwb + 4];
                #pragma unroll
                for (int nb = 0; nb < 8; nb++) {
                    int j = n0 + nb * 8 + gr;
                    uint32_t b0 = w1W[j * W1T_W + kwb];
                    uint32_t b1f = w1W[j * W1T_W + kwb + 4];
                    mma16816(acc[nb][0], acc[nb][1], acc[nb][2], acc[nb][3],
                             a0, a1, a2, a3, b0, b1f);
                }
            }
            #pragma unroll
            for (int nb = 0; nb < 8; nb++) {
                int j = n0 + nb * 8 + 2 * tc;
                float2 bb = *(const float2*)(b1s + j);
                float f0 = fmaxf(acc[nb][0] + bb.x, 0.f);
                float f1 = fmaxf(acc[nb][1] + bb.y, 0.f);
                float f2 = fmaxf(acc[nb][2] + bb.x, 0.f);
                float f3 = fmaxf(acc[nb][3] + bb.y, 0.f);
                int jw = (n0 + nb * 8) / 2 + tc;
                zsW[(m0 + gr) * ZS_W + jw]     = pack_h2(f0, f1);
                zsW[(m0 + gr + 8) * ZS_W + jw] = pack_h2(f2, f3);
            }
        }
        __syncthreads();

        {
            float acc[3][4];
            #pragma unroll
            for (int nb = 0; nb < 3; nb++)
                #pragma unroll
                for (int q = 0; q < 4; q++) acc[nb][q] = 0.f;

            #pragma unroll 4
            for (int kb = 0; kb < 16; kb++) {
                int kwb = kb * 8 + tc;
                uint32_t a0 = zsW[(m0 + gr) * ZS_W + kwb];
                uint32_t a1 = zsW[(m0 + gr + 8) * ZS_W + kwb];
                uint32_t a2 = zsW[(m0 + gr) * ZS_W + kwb + 4];
                uint32_t a3 = zsW[(m0 + gr + 8) * ZS_W + kwb + 4];
                #pragma unroll
                for (int nb = 0; nb < 3; nb++) {
                    int c = (half * 3 + nb) * 8 + gr;
                    uint32_t b0 = w2W[c * W2T_W + kwb];
                    uint32_t b1f = w2W[c * W2T_W + kwb + 4];
                    mma16816(acc[nb][0], acc[nb][1], acc[nb][2], acc[nb][3],
                             a0, a1, a2, a3, b0, b1f);
                }
            }

            int nodeA = node0 + m0 + gr;
            int nodeB = nodeA + 8;
            #pragma unroll
            for (int nb = 0; nb < 3; nb++) {
                int c = (half * 3 + nb) * 8 + 2 * tc;
                if (c < N_CLS) {
                    float bc = b2s[c];
                    if (nodeA < N_NODES) out[(size_t)nodeA * N_CLS + c] = acc[nb][0] + bc;
                    if (nodeB < N_NODES) out[(size_t)nodeB * N_CLS + c] = acc[nb][2] + bc;
                }
                if (c + 1 < N_CLS) {
                    float bc = b2s[c + 1];
                    if (nodeA < N_NODES) out[(size_t)nodeA * N_CLS + c + 1] = acc[nb][1] + bc;
                    if (nodeB < N_NODES) out[(size_t)nodeB * N_CLS + c + 1] = acc[nb][3] + bc;
                }
            }
        }
        __syncthreads();
    }
}

// ---------------- launch ----------------
extern "C" void kernel_launch(void* const* d_in, const int* in_sizes, int n_in,
                              void* d_out, int out_size) {
    const float* x   = (const float*)d_in[0];
    const int*   src = (const int*)d_in[1];
    const int*   dst = (const int*)d_in[2];
    const float* W1  = (const float*)d_in[3];
    const float* b1  = (const float*)d_in[4];
    const float* W2  = (const float*)d_in[5];
    const float* b2  = (const float*)d_in[6];
    float* out = (float*)d_out;

    cudaFuncSetAttribute(mlp_mma_kernel, cudaFuncAttributeMaxDynamicSharedMemorySize,
                         MLP_SMEM_BYTES);

    float* p0 = nullptr;
    float* p1 = nullptr;
    __half* pxh = nullptr;
    cudaGetSymbolAddress((void**)&p0, g_buf0);
    cudaGetSymbolAddress((void**)&p1, g_buf1);
    cudaGetSymbolAddress((void**)&pxh, g_xnh);

    int nb_edges = (N_EDGES + 255) / 256;       // 3125
    int nb_prop = (N_NODES * 32 + 63) / 64;     // 64-thread blocks, warp per node

    count_kernel<<<nb_edges, 256>>>(dst);                           // launch 0
    scan_kernel<<<1, SCAN_T>>>();                                   // launch 1
    fill_kernel<<<nb_edges, 256>>>(src, dst, (const float4*)x);     // launch 2 (+buf0/xnh)

    // t = 0..9: ping-pong buf0 <-> buf1; term = xnh fp16 (last: x fp32)
    // launch 3 (profiled) = t=0: gathers buf0 (40MB) + term xnh (20MB) + writes buf1
    //   -> representative of every steady-state step.
    for (int t = 0; t < K_STEPS; t++) {
        const float* gin = (t & 1) ? p1 : p0;
        float* gout      = (t & 1) ? p0 : p1;
        int last = (t == K_STEPS - 1);
        prop_kernel<<<nb_prop, 64>>>((const char*)gin, (float4*)gout,
                                     (const uint2*)pxh, (const float4*)x, last);
    }
    // t=9 (odd) wrote p0 -> h lives in g_buf0
    mlp_mma_kernel<<<148, MLP_THREADS, MLP_SMEM_BYTES>>>(p0, W1, b1, W2, b2, out);
}

// round 15
// speedup vs baseline: 1.2308x; 1.2308x over previous
#include <cuda_runtime.h>
#include <cuda_bf16.h>
#include <cuda_fp16.h>
#include <math.h>
#include <stdint.h>

#define N_NODES 100000
#define N_EDGES 800000
#define D_DATA  100
#define H_DIM   256
#define N_CLS   47
#define K_STEPS 10
#define D_VEC   25
// fp16 state rows: 128 halves (256 bytes), features 0..99 data, 100.. zero pad
#define ROW_U4  16            // uint4 slots per row

// ---------------- static device scratch ----------------
__device__ uint4  g_h0[(size_t)N_NODES * ROW_U4];    // 25.6 MB fp16 state
__device__ uint4  g_h1[(size_t)N_NODES * ROW_U4];    // 25.6 MB fp16 state
__device__ uint4  g_xnh[(size_t)N_NODES * ROW_U4];   // 25.6 MB fp16 norm*x
__device__ uint4  g_xh[(size_t)N_NODES * ROW_U4];    // 25.6 MB fp16 x
__device__ int    d_cnt[N_NODES];
__device__ int2   d_ptr2[N_NODES];                   // (begin, end)
__device__ int    d_cursor[N_NODES];
__device__ float  d_norm[N_NODES];
__device__ float  d_n2[N_NODES];
__device__ int    d_csr[N_EDGES];                    // BYTE offsets: src << 8

// ---------------- CSR build ----------------
__global__ void count_kernel(const int* __restrict__ dst) {
    int e = blockIdx.x * blockDim.x + threadIdx.x;
    if (e < N_EDGES) atomicAdd(&d_cnt[dst[e]], 1);
}

#define SCAN_T 1024
#define SCAN_CH 98
__global__ void scan_kernel() {
    __shared__ int part[SCAN_T];
    int t = threadIdx.x;
    int beg = t * SCAN_CH;
    int end = beg + SCAN_CH; if (end > N_NODES) end = N_NODES;
    if (beg > N_NODES) beg = N_NODES;
    int s = 0;
    for (int i = beg; i < end; i++) s += d_cnt[i];
    part[t] = s;
    __syncthreads();
    for (int off = 1; off < SCAN_T; off <<= 1) {
        int v = (t >= off) ? part[t - off] : 0;
        __syncthreads();
        part[t] += v;
        __syncthreads();
    }
    int run = part[t] - s;
    for (int i = beg; i < end; i++) {
        int c = d_cnt[i];
        d_ptr2[i] = make_int2(run, run + c);
        d_cursor[i] = run;
        run += c;
        float nm = rsqrtf(fmaxf((float)c, 1.0f));
        d_norm[i] = nm;
        d_n2[i] = nm * nm;
    }
}

__device__ __forceinline__ uint32_t pack_h2(float lo, float hi) {
    __half2 h = __floats2half2_rn(lo, hi);
    return *(uint32_t*)&h;
}

// scatter byte offsets into CSR; zero d_cnt; build xnh (norm*x) and xh (x) fp16 rows
#define FILL_THREADS_TOTAL (3125 * 256)   // == N_EDGES
__global__ void fill_kernel(const int* __restrict__ src, const int* __restrict__ dst,
                            const float2* __restrict__ x2) {
    int e = blockIdx.x * blockDim.x + threadIdx.x;
    if (e < N_EDGES) {
        int d = dst[e];
        int p = atomicAdd(&d_cursor[d], 1);
        d_csr[p] = src[e] << 8;
    }
    if (e < N_NODES) d_cnt[e] = 0;
    for (int i = e; i < N_NODES * ROW_U4; i += FILL_THREADS_TOTAL) {
        int node = i >> 4, hl = i & 15;
        uint4 vn = make_uint4(0, 0, 0, 0);
        uint4 vx = make_uint4(0, 0, 0, 0);
        if (hl < 13) {
            float nm = d_norm[node];
            const float2* xr = x2 + (size_t)node * 50;   // 50 float2 per row
            unsigned int wn[4], wx[4];
            #pragma unroll
            for (int p = 0; p < 4; p++) {
                int f2i = 4 * hl + p;                    // float2 index in row
                float2 f = (f2i < 50) ? xr[f2i] : make_float2(0.f, 0.f);
                wx[p] = pack_h2(f.x, f.y);
                wn[p] = pack_h2(nm * f.x, nm * f.y);
            }
            vn = make_uint4(wn[0], wn[1], wn[2], wn[3]);
            vx = make_uint4(wx[0], wx[1], wx[2], wx[3]);
        }
        g_xnh[i] = vn;
        g_xh[i] = vx;
    }
}

// ---------------- propagation: fp16 state, 2 nodes per warp ----------------
// gout = s1 * sum_e gin[src] + 0.1 * term    (fp32 accumulation, fp16 store)
//   t < K-1: s1 = 0.9*n2[i], term = xnh
//   t = K-1: s1 = 0.9*norm[i], term = xh  (h output, fp16 for MLP)
__global__ void prop_kernel(const char* __restrict__ gin,
                            uint4* __restrict__ gout,
                            const uint4* __restrict__ term,
                            int last) {
    int warp = (blockIdx.x * blockDim.x + threadIdx.x) >> 5;
    int lane = threadIdx.x & 31;
    if (warp >= N_NODES / 2) return;
    int half = lane >> 4, hl = lane & 15;
    int node = warp * 2 + half;

    int2 pe = __ldg(&d_ptr2[node]);
    int nH = pe.y - pe.x;
    int nMax = max(nH, __shfl_xor_sync(0xffffffffu, nH, 16));

    bool act = hl < 13;
    const char* gbl = gin + hl * 16;

    float a0 = 0.f, a1 = 0.f, a2 = 0.f, a3 = 0.f;
    float a4 = 0.f, a5 = 0.f, a6 = 0.f, a7 = 0.f;

    for (int base = 0; base < nMax; base += 16) {
        int off = 0;
        if (base + hl < nH) off = __ldg(&d_csr[pe.x + base + hl]);
        int lim = nMax - base; if (lim > 16) lim = 16;
        #pragma unroll 4
        for (int e = 0; e < lim; e++) {
            int o = __shfl_sync(0xffffffffu, off, e, 16);   // broadcast within half
            if (act && (base + e) < nH) {
                uint4 v = *(const uint4*)(gbl + o);
                float2 f0 = __half22float2(*(__half2*)&v.x);
                float2 f1 = __half22float2(*(__half2*)&v.y);
                float2 f2 = __half22float2(*(__half2*)&v.z);
                float2 f3 = __half22float2(*(__half2*)&v.w);
                a0 += f0.x; a1 += f0.y; a2 += f1.x; a3 += f1.y;
                a4 += f2.x; a5 += f2.y; a6 += f3.x; a7 += f3.y;
            }
        }
    }

    if (act) {
        float s1 = 0.9f * (last ? __ldg(&d_norm[node]) : __ldg(&d_n2[node]));
        uint4 t = __ldcs(&term[node * ROW_U4 + hl]);
        float2 t0 = __half22float2(*(__half2*)&t.x);
        float2 t1 = __half22float2(*(__half2*)&t.y);
        float2 t2 = __half22float2(*(__half2*)&t.z);
        float2 t3 = __half22float2(*(__half2*)&t.w);
        uint4 w;
        w.x = pack_h2(s1 * a0 + 0.1f * t0.x, s1 * a1 + 0.1f * t0.y);
        w.y = pack_h2(s1 * a2 + 0.1f * t1.x, s1 * a3 + 0.1f * t1.y);
        w.z = pack_h2(s1 * a4 + 0.1f * t2.x, s1 * a5 + 0.1f * t2.y);
        w.w = pack_h2(s1 * a6 + 0.1f * t3.x, s1 * a7 + 0.1f * t3.y);
        gout[node * ROW_U4 + hl] = w;
    }
}

// ---------------- MLP via warp-level mma.sync (fp16 in, fp32 accum) ----------
// h input now fp16 rows of 64 words (halves 100+ are zero).
#define TILE_M 128
#define MLP_THREADS 512
#define HS_W   60
#define W1T_W  60
#define ZS_W   132
#define W2T_W  132

#define OFF_HS   0
#define OFF_W1T  30720
#define OFF_ZS   92160
#define OFF_W2T  159744
#define OFF_B1   185088
#define OFF_B2   186112
#define MLP_SMEM_BYTES 186304

__device__ __forceinline__ void mma16816(float& c0, float& c1, float& c2, float& c3,
                                         uint32_t a0, uint32_t a1, uint32_t a2, uint32_t a3,
                                         uint32_t b0, uint32_t b1) {
    asm volatile(
        "mma.sync.aligned.m16n8k16.row.col.f32.f16.f16.f32 "
        "{%0,%1,%2,%3}, {%4,%5,%6,%7}, {%8,%9}, {%0,%1,%2,%3};"
        : "+f"(c0), "+f"(c1), "+f"(c2), "+f"(c3)
        : "r"(a0), "r"(a1), "r"(a2), "r"(a3), "r"(b0), "r"(b1));
}

__global__ void __launch_bounds__(MLP_THREADS, 1)
mlp_mma_kernel(const uint32_t* __restrict__ h16,      // fp16 rows, 64 words stride
               const float* __restrict__ W1, const float* __restrict__ b1,
               const float* __restrict__ W2, const float* __restrict__ b2,
               float* __restrict__ out) {
    extern __shared__ char smc[];
    uint32_t* hsW  = (uint32_t*)(smc + OFF_HS);
    uint32_t* w1W  = (uint32_t*)(smc + OFF_W1T);
    uint32_t* zsW  = (uint32_t*)(smc + OFF_ZS);
    uint32_t* w2W  = (uint32_t*)(smc + OFF_W2T);
    float*    b1s  = (float*)(smc + OFF_B1);
    float*    b2s  = (float*)(smc + OFF_B2);

    int tid = threadIdx.x;
    int wid = tid >> 5, lane = tid & 31;
    int gr = lane >> 2, tc = lane & 3;
    int wp = wid >> 1, half = wid & 1;
    int m0 = wp * 16;

    for (int i = tid; i < 256 * W1T_W; i += MLP_THREADS) {
        int j = i / W1T_W, kw = i % W1T_W;
        int k = kw * 2;
        float lo = (k     < D_DATA) ? W1[k * H_DIM + j]       : 0.f;
        float hi = (k + 1 < D_DATA) ? W1[(k + 1) * H_DIM + j] : 0.f;
        w1W[i] = pack_h2(lo, hi);
    }
    for (int i = tid; i < 48 * W2T_W; i += MLP_THREADS) {
        int c = i / W2T_W, jw = i % W2T_W;
        int j = jw * 2;
        float lo = (c < N_CLS && j     < H_DIM) ? W2[j * N_CLS + c]       : 0.f;
        float hi = (c < N_CLS && j + 1 < H_DIM) ? W2[(j + 1) * N_CLS + c] : 0.f;
        w2W[i] = pack_h2(lo, hi);
    }
    for (int i = tid; i < H_DIM; i += MLP_THREADS) b1s[i] = b1[i];
    if (tid < 48) b2s[tid] = (tid < N_CLS) ? b2[tid] : 0.f;
    __syncthreads();

    int n_tiles = (N_NODES + TILE_M - 1) / TILE_M;   // 782
    for (int tile = blockIdx.x; tile < n_tiles; tile += gridDim.x) {
        int node0 = tile * TILE_M;

        // stage hs: direct fp16 word copy (pads already zero in source)
        for (int i = tid; i < TILE_M * HS_W; i += MLP_THREADS) {
            int m = i / HS_W, kw = i % HS_W;
            int node = node0 + m;
            hsW[i] = (node < N_NODES) ? __ldcs(&h16[(size_t)node * 64 + kw]) : 0u;
        }
        __syncthreads();

        #pragma unroll 1
        for (int chh = 0; chh < 2; chh++) {
            int n0 = (half * 2 + chh) * 64;
            float acc[8][4];
            #pragma unroll
            for (int nb = 0; nb < 8; nb++)
                #pragma unroll
                for (int q = 0; q < 4; q++) acc[nb][q] = 0.f;

            #pragma unroll
            for (int kb = 0; kb < 7; kb++) {
                int kwb = kb * 8 + tc;
                uint32_t a0 = hsW[(m0 + gr) * HS_W + kwb];
                uint32_t a1 = hsW[(m0 + gr + 8) * HS_W + kwb];
                uint32_t a2 = hsW[(m0 + gr) * HS_W + kwb + 4];
                uint32_t a3 = hsW[(m0 + gr + 8) * HS_W + kwb + 4];
                #pragma unroll
                for (int nb = 0; nb < 8; nb++) {
                    int j = n0 + nb * 8 + gr;
                    uint32_t b0 = w1W[j * W1T_W + kwb];
                    uint32_t b1f = w1W[j * W1T_W + kwb + 4];
                    mma16816(acc[nb][0], acc[nb][1], acc[nb][2], acc[nb][3],
                             a0, a1, a2, a3, b0, b1f);
                }
            }
            #pragma unroll
            for (int nb = 0; nb < 8; nb++) {
                int j = n0 + nb * 8 + 2 * tc;
                float2 bb = *(const float2*)(b1s + j);
                float f0 = fmaxf(acc[nb][0] + bb.x, 0.f);
                float f1 = fmaxf(acc[nb][1] + bb.y, 0.f);
                float f2 = fmaxf(acc[nb][2] + bb.x, 0.f);
                float f3 = fmaxf(acc[nb][3] + bb.y, 0.f);
                int jw = (n0 + nb * 8) / 2 + tc;
                zsW[(m0 + gr) * ZS_W + jw]     = pack_h2(f0, f1);
                zsW[(m0 + gr + 8) * ZS_W + jw] = pack_h2(f2, f3);
            }
        }
        __syncthreads();

        {
            float acc[3][4];
            #pragma unroll
            for (int nb = 0; nb < 3; nb++)
                #pragma unroll
                for (int q = 0; q < 4; q++) acc[nb][q] = 0.f;

            #pragma unroll 4
            for (int kb = 0; kb < 16; kb++) {
                int kwb = kb * 8 + tc;
                uint32_t a0 = zsW[(m0 + gr) * ZS_W + kwb];
                uint32_t a1 = zsW[(m0 + gr + 8) * ZS_W + kwb];
                uint32_t a2 = zsW[(m0 + gr) * ZS_W + kwb + 4];
                uint32_t a3 = zsW[(m0 + gr + 8) * ZS_W + kwb + 4];
                #pragma unroll
                for (int nb = 0; nb < 3; nb++) {
                    int c = (half * 3 + nb) * 8 + gr;
                    uint32_t b0 = w2W[c * W2T_W + kwb];
                    uint32_t b1f = w2W[c * W2T_W + kwb + 4];
                    mma16816(acc[nb][0], acc[nb][1], acc[nb][2], acc[nb][3],
                             a0, a1, a2, a3, b0, b1f);
                }
            }

            int nodeA = node0 + m0 + gr;
            int nodeB = nodeA + 8;
            #pragma unroll
            for (int nb = 0; nb < 3; nb++) {
                int c = (half * 3 + nb) * 8 + 2 * tc;
                if (c < N_CLS) {
                    float bc = b2s[c];
                    if (nodeA < N_NODES) out[(size_t)nodeA * N_CLS + c] = acc[nb][0] + bc;
                    if (nodeB < N_NODES) out[(size_t)nodeB * N_CLS + c] = acc[nb][2] + bc;
                }
                if (c + 1 < N_CLS) {
                    float bc = b2s[c + 1];
                    if (nodeA < N_NODES) out[(size_t)nodeA * N_CLS + c + 1] = acc[nb][1] + bc;
                    if (nodeB < N_NODES) out[(size_t)nodeB * N_CLS + c + 1] = acc[nb][3] + bc;
                }
            }
        }
        __syncthreads();
    }
}

// ---------------- launch ----------------
extern "C" void kernel_launch(void* const* d_in, const int* in_sizes, int n_in,
                              void* d_out, int out_size) {
    const float* x   = (const float*)d_in[0];
    const int*   src = (const int*)d_in[1];
    const int*   dst = (const int*)d_in[2];
    const float* W1  = (const float*)d_in[3];
    const float* b1  = (const float*)d_in[4];
    const float* W2  = (const float*)d_in[5];
    const float* b2  = (const float*)d_in[6];
    float* out = (float*)d_out;

    cudaFuncSetAttribute(mlp_mma_kernel, cudaFuncAttributeMaxDynamicSharedMemorySize,
                         MLP_SMEM_BYTES);

    uint4* p0 = nullptr;
    uint4* p1 = nullptr;
    uint4* pxn = nullptr;
    uint4* px = nullptr;
    cudaGetSymbolAddress((void**)&p0, g_h0);
    cudaGetSymbolAddress((void**)&p1, g_h1);
    cudaGetSymbolAddress((void**)&pxn, g_xnh);
    cudaGetSymbolAddress((void**)&px, g_xh);

    int nb_edges = (N_EDGES + 255) / 256;            // 3125
    int nb_prop = (N_NODES / 2 * 32 + 63) / 64;      // 2 nodes/warp, 64-thr blocks

    count_kernel<<<nb_edges, 256>>>(dst);                           // launch 0
    scan_kernel<<<1, SCAN_T>>>();                                   // launch 1
    fill_kernel<<<nb_edges, 256>>>(src, dst, (const float2*)x);     // launch 2

    // t=0 (launch 3, profiled): gathers xnh, writes buf0 — steady-state shape.
    prop_kernel<<<nb_prop, 64>>>((const char*)pxn, p0, pxn, 0);
    for (int t = 1; t < K_STEPS; t++) {
        const uint4* gin = (t & 1) ? p0 : p1;
        uint4* gout      = (t & 1) ? p1 : p0;
        int last = (t == K_STEPS - 1);
        prop_kernel<<<nb_prop, 64>>>((const char*)gin, gout,
                                     last ? px : pxn, last);
    }
    // t=9 (odd) wrote p1 -> h (fp16) lives in g_h1
    mlp_mma_kernel<<<148, MLP_THREADS, MLP_SMEM_BYTES>>>(
        (const uint32_t*)p1, W1, b1, W2, b2, out);
}

// round 16
// speedup vs baseline: 1.2600x; 1.0237x over previous
#include <cuda_runtime.h>
#include <cuda_bf16.h>
#include <cuda_fp16.h>
#include <math.h>
#include <stdint.h>

#define N_NODES 100000
#define N_EDGES 800000
#define D_DATA  100
#define H_DIM   256
#define N_CLS   47
#define K_STEPS 10
#define D_VEC   25
// fp16 state rows: 128 halves (256 bytes), features 0..99 data, 100.. zero pad
#define ROW_U4  16            // uint4 slots per row

// ---------------- static device scratch ----------------
__device__ uint4  g_h0[(size_t)N_NODES * ROW_U4];    // 25.6 MB fp16 state
__device__ uint4  g_h1[(size_t)N_NODES * ROW_U4];    // 25.6 MB fp16 state
__device__ uint4  g_xnh[(size_t)N_NODES * ROW_U4];   // 25.6 MB fp16 norm*x
__device__ uint4  g_xh[(size_t)N_NODES * ROW_U4];    // 25.6 MB fp16 x
__device__ int    d_cnt[N_NODES];
__device__ int2   d_ptr2[N_NODES];                   // (begin, end)
__device__ int    d_cursor[N_NODES];
__device__ float  d_norm[N_NODES];
__device__ float  d_n2[N_NODES];
__device__ int    d_csr[N_EDGES];                    // BYTE offsets: src << 8
__device__ int    d_tile_ctr;                        // MLP work-stealing counter

// ---------------- CSR build ----------------
__global__ void count_kernel(const int* __restrict__ dst) {
    int e = blockIdx.x * blockDim.x + threadIdx.x;
    if (e < N_EDGES) atomicAdd(&d_cnt[dst[e]], 1);
}

#define SCAN_T 1024
#define SCAN_CH 98
__global__ void scan_kernel() {
    __shared__ int part[SCAN_T];
    int t = threadIdx.x;
    int beg = t * SCAN_CH;
    int end = beg + SCAN_CH; if (end > N_NODES) end = N_NODES;
    if (beg > N_NODES) beg = N_NODES;
    int s = 0;
    for (int i = beg; i < end; i++) s += d_cnt[i];
    part[t] = s;
    __syncthreads();
    for (int off = 1; off < SCAN_T; off <<= 1) {
        int v = (t >= off) ? part[t - off] : 0;
        __syncthreads();
        part[t] += v;
        __syncthreads();
    }
    int run = part[t] - s;
    for (int i = beg; i < end; i++) {
        int c = d_cnt[i];
        d_ptr2[i] = make_int2(run, run + c);
        d_cursor[i] = run;
        run += c;
        float nm = rsqrtf(fmaxf((float)c, 1.0f));
        d_norm[i] = nm;
        d_n2[i] = nm * nm;
    }
}

__device__ __forceinline__ uint32_t pack_h2(float lo, float hi) {
    __half2 h = __floats2half2_rn(lo, hi);
    return *(uint32_t*)&h;
}

// scatter byte offsets into CSR; zero d_cnt + tile ctr; build xnh / xh fp16 rows
#define FILL_THREADS_TOTAL (3125 * 256)   // == N_EDGES
__global__ void fill_kernel(const int* __restrict__ src, const int* __restrict__ dst,
                            const float2* __restrict__ x2) {
    int e = blockIdx.x * blockDim.x + threadIdx.x;
    if (e == 0) d_tile_ctr = 0;
    if (e < N_EDGES) {
        int d = dst[e];
        int p = atomicAdd(&d_cursor[d], 1);
        d_csr[p] = src[e] << 8;
    }
    if (e < N_NODES) d_cnt[e] = 0;
    for (int i = e; i < N_NODES * ROW_U4; i += FILL_THREADS_TOTAL) {
        int node = i >> 4, hl = i & 15;
        uint4 vn = make_uint4(0, 0, 0, 0);
        uint4 vx = make_uint4(0, 0, 0, 0);
        if (hl < 13) {
            float nm = d_norm[node];
            const float2* xr = x2 + (size_t)node * 50;
            unsigned int wn[4], wx[4];
            #pragma unroll
            for (int p = 0; p < 4; p++) {
                int f2i = 4 * hl + p;
                float2 f = (f2i < 50) ? xr[f2i] : make_float2(0.f, 0.f);
                wx[p] = pack_h2(f.x, f.y);
                wn[p] = pack_h2(nm * f.x, nm * f.y);
            }
            vn = make_uint4(wn[0], wn[1], wn[2], wn[3]);
            vx = make_uint4(wx[0], wx[1], wx[2], wx[3]);
        }
        g_xnh[i] = vn;
        g_xh[i] = vx;
    }
}

// ---------------- propagation: fp16 state, 2 nodes/warp, HADD2 windows ------
// gout = s1 * sum_e gin[src] + 0.1 * term    (fp16 window-accum, fp32 total)
__global__ void prop_kernel(const char* __restrict__ gin,
                            uint4* __restrict__ gout,
                            const uint4* __restrict__ term,
                            int last) {
    int warp = (blockIdx.x * blockDim.x + threadIdx.x) >> 5;
    int lane = threadIdx.x & 31;
    if (warp >= N_NODES / 2) return;
    int half = lane >> 4, hl = lane & 15;
    int node = warp * 2 + half;

    int2 pe = __ldg(&d_ptr2[node]);
    int nH = pe.y - pe.x;
    int nMax = max(nH, __shfl_xor_sync(0xffffffffu, nH, 16));

    bool act = hl < 13;
    const char* gbl = gin + hl * 16;

    float a0 = 0.f, a1 = 0.f, a2 = 0.f, a3 = 0.f;
    float a4 = 0.f, a5 = 0.f, a6 = 0.f, a7 = 0.f;

    const __half2 z2 = __float2half2_rn(0.f);

    for (int base = 0; base < nMax; base += 16) {
        int off = 0;
        if (base + hl < nH) off = __ldg(&d_csr[pe.x + base + hl]);
        int lim = nMax - base; if (lim > 16) lim = 16;

        __half2 b0 = z2, b1 = z2, b2 = z2, b3 = z2;   // fp16 window accums
        #pragma unroll 4
        for (int e = 0; e < lim; e++) {
            int o = __shfl_sync(0xffffffffu, off, e, 16);
            if (act && (base + e) < nH) {
                uint4 v = *(const uint4*)(gbl + o);
                b0 = __hadd2(b0, *(__half2*)&v.x);
                b1 = __hadd2(b1, *(__half2*)&v.y);
                b2 = __hadd2(b2, *(__half2*)&v.z);
                b3 = __hadd2(b3, *(__half2*)&v.w);
            }
        }
        // flush window into fp32 accumulators
        float2 f0 = __half22float2(b0);
        float2 f1 = __half22float2(b1);
        float2 f2 = __half22float2(b2);
        float2 f3 = __half22float2(b3);
        a0 += f0.x; a1 += f0.y; a2 += f1.x; a3 += f1.y;
        a4 += f2.x; a5 += f2.y; a6 += f3.x; a7 += f3.y;
    }

    if (act) {
        float s1 = 0.9f * (last ? __ldg(&d_norm[node]) : __ldg(&d_n2[node]));
        uint4 t = __ldcs(&term[node * ROW_U4 + hl]);
        float2 t0 = __half22float2(*(__half2*)&t.x);
        float2 t1 = __half22float2(*(__half2*)&t.y);
        float2 t2 = __half22float2(*(__half2*)&t.z);
        float2 t3 = __half22float2(*(__half2*)&t.w);
        uint4 w;
        w.x = pack_h2(s1 * a0 + 0.1f * t0.x, s1 * a1 + 0.1f * t0.y);
        w.y = pack_h2(s1 * a2 + 0.1f * t1.x, s1 * a3 + 0.1f * t1.y);
        w.z = pack_h2(s1 * a4 + 0.1f * t2.x, s1 * a5 + 0.1f * t2.y);
        w.w = pack_h2(s1 * a6 + 0.1f * t3.x, s1 * a7 + 0.1f * t3.y);
        gout[node * ROW_U4 + hl] = w;
    }
}

// ---------------- MLP via warp-level mma.sync (fp16 in, fp32 accum) ----------
#define TILE_M 128
#define MLP_THREADS 512
#define HS_W   60
#define W1T_W  60
#define ZS_W   132
#define W2T_W  132

#define OFF_HS   0
#define OFF_W1T  30720
#define OFF_ZS   92160
#define OFF_W2T  159744
#define OFF_B1   185088
#define OFF_B2   186112
#define MLP_SMEM_BYTES 186304

__device__ __forceinline__ void mma16816(float& c0, float& c1, float& c2, float& c3,
                                         uint32_t a0, uint32_t a1, uint32_t a2, uint32_t a3,
                                         uint32_t b0, uint32_t b1) {
    asm volatile(
        "mma.sync.aligned.m16n8k16.row.col.f32.f16.f16.f32 "
        "{%0,%1,%2,%3}, {%4,%5,%6,%7}, {%8,%9}, {%0,%1,%2,%3};"
        : "+f"(c0), "+f"(c1), "+f"(c2), "+f"(c3)
        : "r"(a0), "r"(a1), "r"(a2), "r"(a3), "r"(b0), "r"(b1));
}

__global__ void __launch_bounds__(MLP_THREADS, 1)
mlp_mma_kernel(const uint32_t* __restrict__ h16,      // fp16 rows, 64 words stride
               const float* __restrict__ W1, const float* __restrict__ b1,
               const float* __restrict__ W2, const float* __restrict__ b2,
               float* __restrict__ out) {
    extern __shared__ char smc[];
    uint32_t* hsW  = (uint32_t*)(smc + OFF_HS);
    uint32_t* w1W  = (uint32_t*)(smc + OFF_W1T);
    uint32_t* zsW  = (uint32_t*)(smc + OFF_ZS);
    uint32_t* w2W  = (uint32_t*)(smc + OFF_W2T);
    float*    b1s  = (float*)(smc + OFF_B1);
    float*    b2s  = (float*)(smc + OFF_B2);
    __shared__ int s_tile;

    int tid = threadIdx.x;
    int wid = tid >> 5, lane = tid & 31;
    int gr = lane >> 2, tc = lane & 3;
    int wp = wid >> 1, half = wid & 1;
    int m0 = wp * 16;

    for (int i = tid; i < 256 * W1T_W; i += MLP_THREADS) {
        int j = i / W1T_W, kw = i % W1T_W;
        int k = kw * 2;
        float lo = (k     < D_DATA) ? W1[k * H_DIM + j]       : 0.f;
        float hi = (k + 1 < D_DATA) ? W1[(k + 1) * H_DIM + j] : 0.f;
        w1W[i] = pack_h2(lo, hi);
    }
    for (int i = tid; i < 48 * W2T_W; i += MLP_THREADS) {
        int c = i / W2T_W, jw = i % W2T_W;
        int j = jw * 2;
        float lo = (c < N_CLS && j     < H_DIM) ? W2[j * N_CLS + c]       : 0.f;
        float hi = (c < N_CLS && j + 1 < H_DIM) ? W2[(j + 1) * N_CLS + c] : 0.f;
        w2W[i] = pack_h2(lo, hi);
    }
    for (int i = tid; i < H_DIM; i += MLP_THREADS) b1s[i] = b1[i];
    if (tid < 48) b2s[tid] = (tid < N_CLS) ? b2[tid] : 0.f;
    __syncthreads();

    int n_tiles = (N_NODES + TILE_M - 1) / TILE_M;   // 782
    for (;;) {
        if (tid == 0) s_tile = atomicAdd(&d_tile_ctr, 1);
        __syncthreads();
        int tile = s_tile;
        if (tile >= n_tiles) break;
        int node0 = tile * TILE_M;

        for (int i = tid; i < TILE_M * HS_W; i += MLP_THREADS) {
            int m = i / HS_W, kw = i % HS_W;
            int node = node0 + m;
            hsW[i] = (node < N_NODES) ? __ldcs(&h16[(size_t)node * 64 + kw]) : 0u;
        }
        __syncthreads();

        #pragma unroll 1
        for (int chh = 0; chh < 2; chh++) {
            int n0 = (half * 2 + chh) * 64;
            float acc[8][4];
            #pragma unroll
            for (int nb = 0; nb < 8; nb++)
                #pragma unroll
                for (int q = 0; q < 4; q++) acc[nb][q] = 0.f;

            #pragma unroll
            for (int kb = 0; kb < 7; kb++) {
                int kwb = kb * 8 + tc;
                uint32_t a0 = hsW[(m0 + gr) * HS_W + kwb];
                uint32_t a1 = hsW[(m0 + gr + 8) * HS_W + kwb];
                uint32_t a2 = hsW[(m0 + gr) * HS_W + kwb + 4];
                uint32_t a3 = hsW[(m0 + gr + 8) * HS_W + kwb + 4];
                #pragma unroll
                for (int nb = 0; nb < 8; nb++) {
                    int j = n0 + nb * 8 + gr;
                    uint32_t b0 = w1W[j * W1T_W + kwb];
                    uint32_t b1f = w1W[j * W1T_W + kwb + 4];
                    mma16816(acc[nb][0], acc[nb][1], acc[nb][2], acc[nb][3],
                             a0, a1, a2, a3, b0, b1f);
                }
            }
            #pragma unroll
            for (int nb = 0; nb < 8; nb++) {
                int j = n0 + nb * 8 + 2 * tc;
                float2 bb = *(const float2*)(b1s + j);
                float f0 = fmaxf(acc[nb][0] + bb.x, 0.f);
                float f1 = fmaxf(acc[nb][1] + bb.y, 0.f);
                float f2 = fmaxf(acc[nb][2] + bb.x, 0.f);
                float f3 = fmaxf(acc[nb][3] + bb.y, 0.f);
                int jw = (n0 + nb * 8) / 2 + tc;
                zsW[(m0 + gr) * ZS_W + jw]     = pack_h2(f0, f1);
                zsW[(m0 + gr + 8) * ZS_W + jw] = pack_h2(f2, f3);
            }
        }
        __syncthreads();

        {
            float acc[3][4];
            #pragma unroll
            for (int nb = 0; nb < 3; nb++)
                #pragma unroll
                for (int q = 0; q < 4; q++) acc[nb][q] = 0.f;

            #pragma unroll 4
            for (int kb = 0; kb < 16; kb++) {
                int kwb = kb * 8 + tc;
                uint32_t a0 = zsW[(m0 + gr) * ZS_W + kwb];
                uint32_t a1 = zsW[(m0 + gr + 8) * ZS_W + kwb];
                uint32_t a2 = zsW[(m0 + gr) * ZS_W + kwb + 4];
                uint32_t a3 = zsW[(m0 + gr + 8) * ZS_W + kwb + 4];
                #pragma unroll
                for (int nb = 0; nb < 3; nb++) {
                    int c = (half * 3 + nb) * 8 + gr;
                    uint32_t b0 = w2W[c * W2T_W + kwb];
                    uint32_t b1f = w2W[c * W2T_W + kwb + 4];
                    mma16816(acc[nb][0], acc[nb][1], acc[nb][2], acc[nb][3],
                             a0, a1, a2, a3, b0, b1f);
                }
            }

            int nodeA = node0 + m0 + gr;
            int nodeB = nodeA + 8;
            #pragma unroll
            for (int nb = 0; nb < 3; nb++) {
                int c = (half * 3 + nb) * 8 + 2 * tc;
                if (c < N_CLS) {
                    float bc = b2s[c];
                    if (nodeA < N_NODES) out[(size_t)nodeA * N_CLS + c] = acc[nb][0] + bc;
                    if (nodeB < N_NODES) out[(size_t)nodeB * N_CLS + c] = acc[nb][2] + bc;
                }
                if (c + 1 < N_CLS) {
                    float bc = b2s[c + 1];
                    if (nodeA < N_NODES) out[(size_t)nodeA * N_CLS + c + 1] = acc[nb][1] + bc;
                    if (nodeB < N_NODES) out[(size_t)nodeB * N_CLS + c + 1] = acc[nb][3] + bc;
                }
            }
        }
        __syncthreads();
    }
}

// ---------------- launch ----------------
extern "C" void kernel_launch(void* const* d_in, const int* in_sizes, int n_in,
                              void* d_out, int out_size) {
    const float* x   = (const float*)d_in[0];
    const int*   src = (const int*)d_in[1];
    const int*   dst = (const int*)d_in[2];
    const float* W1  = (const float*)d_in[3];
    const float* b1  = (const float*)d_in[4];
    const float* W2  = (const float*)d_in[5];
    const float* b2  = (const float*)d_in[6];
    float* out = (float*)d_out;

    cudaFuncSetAttribute(mlp_mma_kernel, cudaFuncAttributeMaxDynamicSharedMemorySize,
                         MLP_SMEM_BYTES);

    uint4* p0 = nullptr;
    uint4* p1 = nullptr;
    uint4* pxn = nullptr;
    uint4* px = nullptr;
    cudaGetSymbolAddress((void**)&p0, g_h0);
    cudaGetSymbolAddress((void**)&p1, g_h1);
    cudaGetSymbolAddress((void**)&pxn, g_xnh);
    cudaGetSymbolAddress((void**)&px, g_xh);

    int nb_edges = (N_EDGES + 255) / 256;            // 3125
    int nb_prop = (N_NODES / 2 * 32 + 63) / 64;      // 2 nodes/warp, 64-thr blocks

    count_kernel<<<nb_edges, 256>>>(dst);                           // launch 0
    scan_kernel<<<1, SCAN_T>>>();                                   // launch 1
    fill_kernel<<<nb_edges, 256>>>(src, dst, (const float2*)x);     // launch 2

    // t=0 (launch 3, profiled): steady-state shape
    prop_kernel<<<nb_prop, 64>>>((const char*)pxn, p0, pxn, 0);
    for (int t = 1; t < K_STEPS; t++) {
        const uint4* gin = (t & 1) ? p0 : p1;
        uint4* gout      = (t & 1) ? p1 : p0;
        int last = (t == K_STEPS - 1);
        prop_kernel<<<nb_prop, 64>>>((const char*)gin, gout,
                                     last ? px : pxn, last);
    }
    // t=9 (odd) wrote p1 -> h (fp16) lives in g_h1
    mlp_mma_kernel<<<148, MLP_THREADS, MLP_SMEM_BYTES>>>(
        (const uint32_t*)p1, W1, b1, W2, b2, out);
}

// round 17
// speedup vs baseline: 1.3344x; 1.0591x over previous
#include <cuda_runtime.h>
#include <cuda_bf16.h>
#include <cuda_fp16.h>
#include <math.h>
#include <stdint.h>

#define N_NODES 100000
#define N_EDGES 800000
#define D_DATA  100
#define H_DIM   256
#define N_CLS   47
#define K_STEPS 10
#define D_VEC   25
// fp16 state rows: 128 halves (256 bytes), features 0..99 data, 100.. zero pad
#define ROW_U4  16            // uint4 slots per row

// ---------------- static device scratch ----------------
__device__ uint4  g_h0[(size_t)N_NODES * ROW_U4];    // 25.6 MB fp16 state
__device__ uint4  g_h1[(size_t)N_NODES * ROW_U4];    // 25.6 MB fp16 state
__device__ uint4  g_xnh[(size_t)N_NODES * ROW_U4];   // 25.6 MB fp16 norm*x
__device__ int    d_cnt[N_NODES];
__device__ int2   d_ptr2[N_NODES];                   // (begin, end)
__device__ int    d_cursor[N_NODES];
__device__ float  d_norm[N_NODES];
__device__ int    d_csr[N_EDGES];                    // BYTE offsets: src << 8
__device__ int    d_tile_ctr;                        // MLP work-stealing counter

// ---------------- CSR build ----------------
__global__ void count_kernel(const int* __restrict__ dst) {
    int e = blockIdx.x * blockDim.x + threadIdx.x;
    if (e < N_EDGES) atomicAdd(&d_cnt[dst[e]], 1);
}

#define SCAN_T 1024
#define SCAN_CH 98
__global__ void scan_kernel() {
    __shared__ int part[SCAN_T];
    int t = threadIdx.x;
    int beg = t * SCAN_CH;
    int end = beg + SCAN_CH; if (end > N_NODES) end = N_NODES;
    if (beg > N_NODES) beg = N_NODES;
    int s = 0;
    for (int i = beg; i < end; i++) s += d_cnt[i];
    part[t] = s;
    __syncthreads();
    for (int off = 1; off < SCAN_T; off <<= 1) {
        int v = (t >= off) ? part[t - off] : 0;
        __syncthreads();
        part[t] += v;
        __syncthreads();
    }
    int run = part[t] - s;
    for (int i = beg; i < end; i++) {
        int c = d_cnt[i];
        d_ptr2[i] = make_int2(run, run + c);
        d_cursor[i] = run;
        run += c;
        d_norm[i] = rsqrtf(fmaxf((float)c, 1.0f));
    }
}

__device__ __forceinline__ uint32_t pack_h2(float lo, float hi) {
    __half2 h = __floats2half2_rn(lo, hi);
    return *(uint32_t*)&h;
}

// scatter byte offsets into CSR; zero d_cnt + tile ctr; build xnh fp16 rows
#define FILL_THREADS_TOTAL (3125 * 256)   // == N_EDGES
__global__ void fill_kernel(const int* __restrict__ src, const int* __restrict__ dst,
                            const float2* __restrict__ x2) {
    int e = blockIdx.x * blockDim.x + threadIdx.x;
    if (e == 0) d_tile_ctr = 0;
    if (e < N_EDGES) {
        int d = dst[e];
        int p = atomicAdd(&d_cursor[d], 1);
        d_csr[p] = src[e] << 8;
    }
    if (e < N_NODES) d_cnt[e] = 0;
    for (int i = e; i < N_NODES * ROW_U4; i += FILL_THREADS_TOTAL) {
        int node = i >> 4, hl = i & 15;
        uint4 vn = make_uint4(0, 0, 0, 0);
        if (hl < 13) {
            float nm = d_norm[node];
            const float2* xr = x2 + (size_t)node * 50;
            unsigned int wn[4];
            #pragma unroll
            for (int p = 0; p < 4; p++) {
                int f2i = 4 * hl + p;
                float2 f = (f2i < 50) ? xr[f2i] : make_float2(0.f, 0.f);
                wn[p] = pack_h2(nm * f.x, nm * f.y);
            }
            vn = make_uint4(wn[0], wn[1], wn[2], wn[3]);
        }
        g_xnh[i] = vn;
    }
}

// ---------------- propagation: fp16 state, 2 nodes/warp, HADD2 windows ------
// gout = s1 * sum_e gin[src] + s2 * xnh
//   t < K-1: s1 = 0.9*nrm^2, s2 = 0.1        (g-space; term xnh = nrm*x)
//   t = K-1: s1 = 0.9*nrm,   s2 = 0.1/nrm    (h output: 0.1*x = xnh/nrm * 0.1)
__global__ void __launch_bounds__(64, 28)
prop_kernel(const char* __restrict__ gin,
            uint4* __restrict__ gout,
            const uint4* __restrict__ term,
            int last) {
    int warp = (blockIdx.x * blockDim.x + threadIdx.x) >> 5;
    int lane = threadIdx.x & 31;
    if (warp >= N_NODES / 2) return;
    int half = lane >> 4, hl = lane & 15;
    int node = warp * 2 + half;

    // independent loads up front — overlap with the dependent gather chain
    uint4 t = __ldcs(&term[node * ROW_U4 + hl]);
    float nrm = __ldg(&d_norm[node]);
    int2 pe = __ldg(&d_ptr2[node]);
    int nH = pe.y - pe.x;
    int nMax = max(nH, __shfl_xor_sync(0xffffffffu, nH, 16));

    bool act = hl < 13;
    const char* gbl = gin + hl * 16;

    float a0 = 0.f, a1 = 0.f, a2 = 0.f, a3 = 0.f;
    float a4 = 0.f, a5 = 0.f, a6 = 0.f, a7 = 0.f;

    const __half2 z2 = __float2half2_rn(0.f);

    for (int base = 0; base < nMax; base += 16) {
        int off = 0;
        if (base + hl < nH) off = __ldg(&d_csr[pe.x + base + hl]);
        int lim = nMax - base; if (lim > 16) lim = 16;

        __half2 b0 = z2, b1 = z2, b2 = z2, b3 = z2;   // fp16 window accums
        #pragma unroll 4
        for (int e = 0; e < lim; e++) {
            int o = __shfl_sync(0xffffffffu, off, e, 16);
            if (act && (base + e) < nH) {
                uint4 v = *(const uint4*)(gbl + o);
                b0 = __hadd2(b0, *(__half2*)&v.x);
                b1 = __hadd2(b1, *(__half2*)&v.y);
                b2 = __hadd2(b2, *(__half2*)&v.z);
                b3 = __hadd2(b3, *(__half2*)&v.w);
            }
        }
        float2 f0 = __half22float2(b0);
        float2 f1 = __half22float2(b1);
        float2 f2 = __half22float2(b2);
        float2 f3 = __half22float2(b3);
        a0 += f0.x; a1 += f0.y; a2 += f1.x; a3 += f1.y;
        a4 += f2.x; a5 += f2.y; a6 += f3.x; a7 += f3.y;
    }

    if (act) {
        float s1 = 0.9f * (last ? nrm : nrm * nrm);
        float s2 = last ? (0.1f / nrm) : 0.1f;
        float2 t0 = __half22float2(*(__half2*)&t.x);
        float2 t1 = __half22float2(*(__half2*)&t.y);
        float2 t2 = __half22float2(*(__half2*)&t.z);
        float2 t3 = __half22float2(*(__half2*)&t.w);
        uint4 w;
        w.x = pack_h2(s1 * a0 + s2 * t0.x, s1 * a1 + s2 * t0.y);
        w.y = pack_h2(s1 * a2 + s2 * t1.x, s1 * a3 + s2 * t1.y);
        w.z = pack_h2(s1 * a4 + s2 * t2.x, s1 * a5 + s2 * t2.y);
        w.w = pack_h2(s1 * a6 + s2 * t3.x, s1 * a7 + s2 * t3.y);
        gout[node * ROW_U4 + hl] = w;
    }
}

// ---------------- MLP via warp-level mma.sync (fp16 in, fp32 accum) ----------
#define TILE_M 128
#define MLP_THREADS 512
#define HS_W   60
#define W1T_W  60
#define ZS_W   132
#define W2T_W  132

#define OFF_HS   0
#define OFF_W1T  30720
#define OFF_ZS   92160
#define OFF_W2T  159744
#define OFF_B1   185088
#define OFF_B2   186112
#define MLP_SMEM_BYTES 186304

__device__ __forceinline__ void mma16816(float& c0, float& c1, float& c2, float& c3,
                                         uint32_t a0, uint32_t a1, uint32_t a2, uint32_t a3,
                                         uint32_t b0, uint32_t b1) {
    asm volatile(
        "mma.sync.aligned.m16n8k16.row.col.f32.f16.f16.f32 "
        "{%0,%1,%2,%3}, {%4,%5,%6,%7}, {%8,%9}, {%0,%1,%2,%3};"
        : "+f"(c0), "+f"(c1), "+f"(c2), "+f"(c3)
        : "r"(a0), "r"(a1), "r"(a2), "r"(a3), "r"(b0), "r"(b1));
}

__global__ void __launch_bounds__(MLP_THREADS, 1)
mlp_mma_kernel(const uint32_t* __restrict__ h16,      // fp16 rows, 64 words stride
               const float* __restrict__ W1, const float* __restrict__ b1,
               const float* __restrict__ W2, const float* __restrict__ b2,
               float* __restrict__ out) {
    extern __shared__ char smc[];
    uint32_t* hsW  = (uint32_t*)(smc + OFF_HS);
    uint32_t* w1W  = (uint32_t*)(smc + OFF_W1T);
    uint32_t* zsW  = (uint32_t*)(smc + OFF_ZS);
    uint32_t* w2W  = (uint32_t*)(smc + OFF_W2T);
    float*    b1s  = (float*)(smc + OFF_B1);
    float*    b2s  = (float*)(smc + OFF_B2);
    __shared__ int s_tile;

    int tid = threadIdx.x;
    int wid = tid >> 5, lane = tid & 31;
    int gr = lane >> 2, tc = lane & 3;
    int wp = wid >> 1, half = wid & 1;
    int m0 = wp * 16;

    for (int i = tid; i < 256 * W1T_W; i += MLP_THREADS) {
        int j = i / W1T_W, kw = i % W1T_W;
        int k = kw * 2;
        float lo = (k     < D_DATA) ? W1[k * H_DIM + j]       : 0.f;
        float hi = (k + 1 < D_DATA) ? W1[(k + 1) * H_DIM + j] : 0.f;
        w1W[i] = pack_h2(lo, hi);
    }
    for (int i = tid; i < 48 * W2T_W; i += MLP_THREADS) {
        int c = i / W2T_W, jw = i % W2T_W;
        int j = jw * 2;
        float lo = (c < N_CLS && j     < H_DIM) ? W2[j * N_CLS + c]       : 0.f;
        float hi = (c < N_CLS && j + 1 < H_DIM) ? W2[(j + 1) * N_CLS + c] : 0.f;
        w2W[i] = pack_h2(lo, hi);
    }
    for (int i = tid; i < H_DIM; i += MLP_THREADS) b1s[i] = b1[i];
    if (tid < 48) b2s[tid] = (tid < N_CLS) ? b2[tid] : 0.f;
    __syncthreads();

    int n_tiles = (N_NODES + TILE_M - 1) / TILE_M;   // 782
    for (;;) {
        if (tid == 0) s_tile = atomicAdd(&d_tile_ctr, 1);
        __syncthreads();
        int tile = s_tile;
        if (tile >= n_tiles) break;
        int node0 = tile * TILE_M;

        for (int i = tid; i < TILE_M * HS_W; i += MLP_THREADS) {
            int m = i / HS_W, kw = i % HS_W;
            int node = node0 + m;
            hsW[i] = (node < N_NODES) ? __ldcs(&h16[(size_t)node * 64 + kw]) : 0u;
        }
        __syncthreads();

        #pragma unroll 1
        for (int chh = 0; chh < 2; chh++) {
            int n0 = (half * 2 + chh) * 64;
            float acc[8][4];
            #pragma unroll
            for (int nb = 0; nb < 8; nb++)
                #pragma unroll
                for (int q = 0; q < 4; q++) acc[nb][q] = 0.f;

            #pragma unroll
            for (int kb = 0; kb < 7; kb++) {
                int kwb = kb * 8 + tc;
                uint32_t a0 = hsW[(m0 + gr) * HS_W + kwb];
                uint32_t a1 = hsW[(m0 + gr + 8) * HS_W + kwb];
                uint32_t a2 = hsW[(m0 + gr) * HS_W + kwb + 4];
                uint32_t a3 = hsW[(m0 + gr + 8) * HS_W + kwb + 4];
                #pragma unroll
                for (int nb = 0; nb < 8; nb++) {
                    int j = n0 + nb * 8 + gr;
                    uint32_t b0 = w1W[j * W1T_W + kwb];
                    uint32_t b1f = w1W[j * W1T_W + kwb + 4];
                    mma16816(acc[nb][0], acc[nb][1], acc[nb][2], acc[nb][3],
                             a0, a1, a2, a3, b0, b1f);
                }
            }
            #pragma unroll
            for (int nb = 0; nb < 8; nb++) {
                int j = n0 + nb * 8 + 2 * tc;
                float2 bb = *(const float2*)(b1s + j);
                float f0 = fmaxf(acc[nb][0] + bb.x, 0.f);
                float f1 = fmaxf(acc[nb][1] + bb.y, 0.f);
                float f2 = fmaxf(acc[nb][2] + bb.x, 0.f);
                float f3 = fmaxf(acc[nb][3] + bb.y, 0.f);
                int jw = (n0 + nb * 8) / 2 + tc;
                zsW[(m0 + gr) * ZS_W + jw]     = pack_h2(f0, f1);
                zsW[(m0 + gr + 8) * ZS_W + jw] = pack_h2(f2, f3);
            }
        }
        __syncthreads();

        {
            float acc[3][4];
            #pragma unroll
            for (int nb = 0; nb < 3; nb++)
                #pragma unroll
                for (int q = 0; q < 4; q++) acc[nb][q] = 0.f;

            #pragma unroll 4
            for (int kb = 0; kb < 16; kb++) {
                int kwb = kb * 8 + tc;
                uint32_t a0 = zsW[(m0 + gr) * ZS_W + kwb];
                uint32_t a1 = zsW[(m0 + gr + 8) * ZS_W + kwb];
                uint32_t a2 = zsW[(m0 + gr) * ZS_W + kwb + 4];
                uint32_t a3 = zsW[(m0 + gr + 8) * ZS_W + kwb + 4];
                #pragma unroll
                for (int nb = 0; nb < 3; nb++) {
                    int c = (half * 3 + nb) * 8 + gr;
                    uint32_t b0 = w2W[c * W2T_W + kwb];
                    uint32_t b1f = w2W[c * W2T_W + kwb + 4];
                    mma16816(acc[nb][0], acc[nb][1], acc[nb][2], acc[nb][3],
                             a0, a1, a2, a3, b0, b1f);
                }
            }

            int nodeA = node0 + m0 + gr;
            int nodeB = nodeA + 8;
            #pragma unroll
            for (int nb = 0; nb < 3; nb++) {
                int c = (half * 3 + nb) * 8 + 2 * tc;
                if (c < N_CLS) {
                    float bc = b2s[c];
                    if (nodeA < N_NODES) out[(size_t)nodeA * N_CLS + c] = acc[nb][0] + bc;
                    if (nodeB < N_NODES) out[(size_t)nodeB * N_CLS + c] = acc[nb][2] + bc;
                }
                if (c + 1 < N_CLS) {
                    float bc = b2s[c + 1];
                    if (nodeA < N_NODES) out[(size_t)nodeA * N_CLS + c + 1] = acc[nb][1] + bc;
                    if (nodeB < N_NODES) out[(size_t)nodeB * N_CLS + c + 1] = acc[nb][3] + bc;
                }
            }
        }
        __syncthreads();
    }
}

// ---------------- launch ----------------
extern "C" void kernel_launch(void* const* d_in, const int* in_sizes, int n_in,
                              void* d_out, int out_size) {
    const float* x   = (const float*)d_in[0];
    const int*   src = (const int*)d_in[1];
    const int*   dst = (const int*)d_in[2];
    const float* W1  = (const float*)d_in[3];
    const float* b1  = (const float*)d_in[4];
    const float* W2  = (const float*)d_in[5];
    const float* b2  = (const float*)d_in[6];
    float* out = (float*)d_out;

    cudaFuncSetAttribute(mlp_mma_kernel, cudaFuncAttributeMaxDynamicSharedMemorySize,
                         MLP_SMEM_BYTES);

    uint4* p0 = nullptr;
    uint4* p1 = nullptr;
    uint4* pxn = nullptr;
    cudaGetSymbolAddress((void**)&p0, g_h0);
    cudaGetSymbolAddress((void**)&p1, g_h1);
    cudaGetSymbolAddress((void**)&pxn, g_xnh);

    int nb_edges = (N_EDGES + 255) / 256;            // 3125
    int nb_prop = (N_NODES / 2 * 32 + 63) / 64;      // 2 nodes/warp, 64-thr blocks

    count_kernel<<<nb_edges, 256>>>(dst);                           // launch 0
    scan_kernel<<<1, SCAN_T>>>();                                   // launch 1
    fill_kernel<<<nb_edges, 256>>>(src, dst, (const float2*)x);     // launch 2

    // t=0 (launch 3, profiled): steady-state shape
    prop_kernel<<<nb_prop, 64>>>((const char*)pxn, p0, pxn, 0);
    for (int t = 1; t < K_STEPS; t++) {
        const uint4* gin = (t & 1) ? p0 : p1;
        uint4* gout      = (t & 1) ? p1 : p0;
        int last = (t == K_STEPS - 1);
        prop_kernel<<<nb_prop, 64>>>((const char*)gin, gout, pxn, last);
    }
    // t=9 (odd) wrote p1 -> h (fp16) lives in g_h1
    mlp_mma_kernel<<<148, MLP_THREADS, MLP_SMEM_BYTES>>>(
        (const uint32_t*)p1, W1, b1, W2, b2, out);
}